// round 7
// baseline (speedup 1.0000x reference)
#include <cuda_runtime.h>

// Problem geometry (fixed by the dataset)
#define WW 256
#define HH 256
#define DD 64
#define HWW (HH*WW)        // 65536
#define CS  (DD*HWW)       // 4194304 elements per (channel, batch-slice)

#define NSEG 8             // d-segments
#define PS   8             // planes per segment (last segment: 6)
#define R    4             // h-rows per thread

// Global accumulators. Static zero-init; final_kernel resets after reading,
// so every graph replay starts from zero (deterministic).
__device__ double g_sum;
__device__ double g_cnt;

__global__ void final_kernel(float* out) {
    out[0] = (float)(g_sum / g_cnt);
    g_sum = 0.0;
    g_cnt = 0.0;
}

__device__ __forceinline__ float4 ldf4(const float* p) {
    return *reinterpret_cast<const float4*>(p);
}

// e = predicts - targets for one channel, vectorized
__device__ __forceinline__ float4 e4(const float* __restrict__ p,
                                     const float* __restrict__ t, int off) {
    float4 a = ldf4(p + off);
    float4 b = ldf4(t + off);
    return make_float4(a.x - b.x, a.y - b.y, a.z - b.z, a.w - b.w);
}

#define GET(v4, i) ((i)==0?(v4).x:((i)==1?(v4).y:((i)==2?(v4).z:(v4).w)))

// Per-plane mask bits for 4 output rows (packed 4 bits per row, 16 bits total).
// Bit (4r+i) set iff the 3x3 (h x w) mask window in plane p around output
// (row r, elem i) is all ones.
__device__ __forceinline__ unsigned maskPlane(const float* __restrict__ Mb, int p,
                                              const int* baseRow, const int* rowW,
                                              bool needL, bool needR) {
    unsigned rb[R + 2];
    const int po = p * HWW;
    #pragma unroll
    for (int j = 0; j < R + 2; ++j) {
        float4 m = ldf4(Mb + po + baseRow[j]);
        float L  = __shfl_up_sync(0xffffffffu, m.w, 1);
        float Rv = __shfl_down_sync(0xffffffffu, m.x, 1);
        if (needL) L  = Mb[po + rowW[j] + 127];
        if (needR) Rv = Mb[po + rowW[j] + 128];
        unsigned bits = 0;
        if (fminf(L,   fminf(m.x, m.y)) > 0.5f) bits |= 1u;
        if (fminf(m.x, fminf(m.y, m.z)) > 0.5f) bits |= 2u;
        if (fminf(m.y, fminf(m.z, m.w)) > 0.5f) bits |= 4u;
        if (fminf(m.z, fminf(m.w, Rv)) > 0.5f)  bits |= 8u;
        rb[j] = bits;
    }
    unsigned out = 0;
    #pragma unroll
    for (int r = 0; r < R; ++r)
        out |= (rb[r] & rb[r + 1] & rb[r + 2]) << (4 * r);
    return out;
}

// One thread owns a 4-wide (float4) strip x R consecutive h-rows at fixed b,
// sliding along a short d-segment. Interior h-neighbors come from registers,
// so u/w3/mask L2 traffic drops from 3x to (R+2)/R x.
__global__ __launch_bounds__(64)
void vort_kernel(const float* __restrict__ P,
                 const float* __restrict__ T,
                 const float* __restrict__ M) {
    const int tid  = threadIdx.x;
    const int lane = tid & 31;
    const int half = tid >> 5;                    // warp in block: 0..1
    const int bx   = blockIdx.x;                  // 0..127 = b*64 + g
    const int b    = bx >> 6;
    const int g    = bx & 63;                     // row group: rows h0..h0+3
    const int h0   = 1 + R * g;                   // 1..253 (g=63 partially valid)
    const int w0   = (half * 32 + lane) * 4;      // 0..252

    const int d0 = 1 + blockIdx.y * PS;
    const int dN = min(d0 + PS, DD - 1);          // exclusive end (<= 63)

    const float* P1 = P + (size_t)b * 4 * CS + CS;
    const float* P2 = P1 + CS;
    const float* P3 = P2 + CS;
    const float* T1 = T + (size_t)b * 4 * CS + CS;
    const float* T2 = T1 + CS;
    const float* T3 = T2 + CS;
    const float* Mb = M + (size_t)b * CS;

    // Row offsets (clamped to the last physical row for the partial tail group)
    int baseRow[R + 2];   // float4-strip base per row j = h0-1+j
    int rowW[R + 2];      // row*WW (for boundary scalar patches)
    #pragma unroll
    for (int j = 0; j < R + 2; ++j) {
        int hj = h0 - 1 + j;
        if (hj > 255) hj = 255;
        rowW[j]    = hj * WW;
        baseRow[j] = hj * WW + w0;
    }

    const bool needR = (half == 0 && lane == 31);   // needs value at w=128
    const bool needL = (half == 1 && lane == 0);    // needs value at w=127

    // Valid-element selector: w boundaries + row validity (packed 4 bits/row)
    unsigned vb = 0xFu;
    if (half == 0 && lane == 0)  vb &= ~1u;   // w=0 excluded
    if (half == 1 && lane == 31) vb &= ~8u;   // w=255 excluded
    unsigned selMask = 0;
    #pragma unroll
    for (int r = 0; r < R; ++r)
        if (h0 + r <= 254) selMask |= vb << (4 * r);

    // Warm-up: planes d0-1 and d0 for u (ch1), v (ch2) slides + mask bits
    float4 u_km1[R], u_k[R], v_km1[R], v_k[R];
    #pragma unroll
    for (int r = 0; r < R; ++r) {
        u_km1[r] = e4(P1, T1, (d0 - 1) * HWW + baseRow[r + 1]);
        u_k[r]   = e4(P1, T1,  d0      * HWW + baseRow[r + 1]);
        v_km1[r] = e4(P2, T2, (d0 - 1) * HWW + baseRow[r + 1]);
        v_k[r]   = e4(P2, T2,  d0      * HWW + baseRow[r + 1]);
    }
    unsigned mA_km1 = maskPlane(Mb, d0 - 1, baseRow, rowW, needL, needR);
    unsigned mA_k   = maskPlane(Mb, d0,     baseRow, rowW, needL, needR);

    float acc = 0.0f;
    int   cnt = 0;

    #pragma unroll 1
    for (int d = d0; d < dN; ++d) {
        const int oN = (d + 1) * HWW;
        const int oC = d * HWW;

        float4 u_kp1[R], v_kp1[R];
        #pragma unroll
        for (int r = 0; r < R; ++r) u_kp1[r] = e4(P1, T1, oN + baseRow[r + 1]);
        #pragma unroll
        for (int r = 0; r < R; ++r) v_kp1[r] = e4(P2, T2, oN + baseRow[r + 1]);
        float4 uTop = e4(P1, T1, oC + baseRow[0]);       // row h0-1, plane d
        float4 uBot = e4(P1, T1, oC + baseRow[R + 1]);   // row h0+R, plane d
        float4 w3row[R + 2];
        #pragma unroll
        for (int j = 0; j < R + 2; ++j) w3row[j] = e4(P3, T3, oC + baseRow[j]);
        unsigned mA_kp1 = maskPlane(Mb, d + 1, baseRow, rowW, needL, needR);

        const unsigned mm_all = mA_km1 & mA_k & mA_kp1 & selMask;

        #pragma unroll
        for (int r = 0; r < R; ++r) {
            const float4 vk  = v_k[r];
            const float4 w3c = w3row[r + 1];

            float v_l  = __shfl_up_sync(0xffffffffu, vk.w, 1);
            float v_r  = __shfl_down_sync(0xffffffffu, vk.x, 1);
            float w3_l = __shfl_up_sync(0xffffffffu, w3c.w, 1);
            float w3_r = __shfl_down_sync(0xffffffffu, w3c.x, 1);
            if (needL) {
                int ix = oC + rowW[r + 1] + 127;
                v_l  = P2[ix] - T2[ix];
                w3_l = P3[ix] - T3[ix];
            }
            if (needR) {
                int ix = oC + rowW[r + 1] + 128;
                v_r  = P2[ix] - T2[ix];
                w3_r = P3[ix] - T3[ix];
            }

            const float4 uhm  = (r == 0)     ? uTop : u_k[r - 1];
            const float4 uhp  = (r == R - 1) ? uBot : u_k[r + 1];
            const float4 w3hm = w3row[r];
            const float4 w3hp = w3row[r + 2];
            const unsigned mm = (mm_all >> (4 * r)) & 0xFu;

            if (mm) {
                #pragma unroll
                for (int i = 0; i < 4; ++i) {
                    float w3l = (i == 0) ? w3_l : GET(w3c, i - 1);
                    float w3r = (i == 3) ? w3_r : GET(w3c, i + 1);
                    float vl  = (i == 0) ? v_l  : GET(vk, i - 1);
                    float vr  = (i == 3) ? v_r  : GET(vk, i + 1);
                    float Ox = (GET(w3hp, i) - GET(w3hm, i)) - (GET(v_kp1[r], i) - GET(v_km1[r], i));
                    float Oy = (GET(u_kp1[r], i) - GET(u_km1[r], i)) - (w3r - w3l);
                    float Oz = (vr - vl) - (GET(uhp, i) - GET(uhm, i));
                    if ((mm >> i) & 1u) {
                        acc += sqrtf(fmaf(Ox, Ox, fmaf(Oy, Oy, Oz * Oz)));
                        cnt++;
                    }
                }
            }
        }

        // slide along d
        #pragma unroll
        for (int r = 0; r < R; ++r) {
            u_km1[r] = u_k[r];  u_k[r] = u_kp1[r];
            v_km1[r] = v_k[r];  v_k[r] = v_kp1[r];
        }
        mA_km1 = mA_k;  mA_k = mA_kp1;
    }

    // Reduction: warp shfl -> smem -> one double atomic pair per block
    #pragma unroll
    for (int o = 16; o; o >>= 1) {
        acc += __shfl_down_sync(0xffffffffu, acc, o);
        cnt += __shfl_down_sync(0xffffffffu, cnt, o);
    }
    __shared__ float sacc[2];
    __shared__ int   scnt[2];
    if (lane == 0) { sacc[half] = acc; scnt[half] = cnt; }
    __syncthreads();
    if (tid == 0) {
        atomicAdd(&g_sum, (double)(sacc[0] + sacc[1]));
        atomicAdd(&g_cnt, (double)(scnt[0] + scnt[1]));
    }
}

extern "C" void kernel_launch(void* const* d_in, const int* in_sizes, int n_in,
                              void* d_out, int out_size) {
    const float* P = (const float*)d_in[0];   // predicts (2,4,64,256,256)
    const float* T = (const float*)d_in[1];   // targets  (2,4,64,256,256)
    const float* M = (const float*)d_in[2];   // masks    (2,1,64,256,256)
    float* out = (float*)d_out;

    dim3 grid(128, NSEG);        // (2 batches x 64 row-groups) x d-segments
    vort_kernel<<<grid, 64>>>(P, T, M);
    final_kernel<<<1, 1>>>(out);
}